// round 1
// baseline (speedup 1.0000x reference)
#include <cuda_runtime.h>

#define NAG   32
#define DIN   256
#define HID   128
#define NACT  32
#define NEGV  9e15f
#define STR   34   // padded inner stride for transposed [dim][agent] tiles

// ---- shared memory layout (floats) ----
#define OFF_XT   0                    // [256][STR] x transposed; later reused as OT [128][STR]
#define OFF_HT   (256*STR)            // [128][STR] current hidden (transposed)
#define OFF_VT   (OFF_HT + 128*STR)
#define OFF_QT   (OFF_VT + 128*STR)
#define OFF_KT   (OFF_QT + 128*STR)
#define OFF_PT   (OFF_KT + 128*STR)   // probs transposed [j][i], [32][STR]
#define OFF_MK   (OFF_PT + 32*STR)    // mask row-major [i][j], [32][32]
#define SMEM_FLOATS (OFF_MK + NAG*NAG)
#define SMEM_BYTES  (SMEM_FLOATS * 4)

// packed fp32x2 FMA: d = a*b + c elementwise on float2 (Blackwell f32x2 pipe, 2 MACs/issue)
__device__ __forceinline__ float2 ffma2v(float2 a, float2 b, float2 c) {
    union F2U { float2 f; unsigned long long u; };
    F2U A, Bv, C, D;
    A.f = a; Bv.f = b; C.f = c;
    asm("fma.rn.f32x2 %0, %1, %2, %3;"
        : "=l"(D.u) : "l"(A.u), "l"(Bv.u), "l"(C.u));
    return D.f;
}

// dstT[t][i] = act(srcT^T @ W + bias) for this thread's column t and 16 rows (8 row-pairs)
// srcT: [K][STR] transposed activations in smem; W: [K][HID] row-major global.
template <bool RELU>
__device__ __forceinline__ void proj_f32x2(
    const float* __restrict__ srcT, int K,
    const float* __restrict__ W, const float* __restrict__ bias,
    float* __restrict__ dstT, int t, int rbase)
{
    float2 acc[8];
#pragma unroll
    for (int p = 0; p < 8; ++p) acc[p] = make_float2(0.f, 0.f);
#pragma unroll 4
    for (int k = 0; k < K; ++k) {
        float w = W[k * HID + t];
        float2 w2 = make_float2(w, w);
        const float2* xr = reinterpret_cast<const float2*>(srcT + k * STR + rbase);
#pragma unroll
        for (int p = 0; p < 8; ++p) acc[p] = ffma2v(xr[p], w2, acc[p]);
    }
    float bb = bias[t];
    float2 b2 = make_float2(bb, bb);
#pragma unroll
    for (int p = 0; p < 8; ++p) {
        float2 r;
        r.x = acc[p].x + b2.x;
        r.y = acc[p].y + b2.y;
        if (RELU) { r.x = fmaxf(r.x, 0.f); r.y = fmaxf(r.y, 0.f); }
        *reinterpret_cast<float2*>(dstT + t * STR + rbase + 2 * p) = r;
    }
}

__device__ __forceinline__ void att_block(
    float* __restrict__ sm,
    const float* __restrict__ vw, const float* __restrict__ vb,
    const float* __restrict__ kw, const float* __restrict__ kb,
    const float* __restrict__ qw, const float* __restrict__ qb,
    const float* __restrict__ ow, const float* __restrict__ ob,
    int tid)
{
    float* sXT = sm + OFF_XT;   // reused here as attention-output (transposed)
    float* sHT = sm + OFF_HT;
    float* sVT = sm + OFF_VT;
    float* sQT = sm + OFF_QT;
    float* sKT = sm + OFF_KT;
    float* sPT = sm + OFF_PT;
    float* sMK = sm + OFF_MK;

    const int t     = tid & 127;         // output column (feature)
    const int rbase = (tid >> 7) << 4;   // 0 or 16: this thread's 16-row slab

    // ---- V, Q, K projections (fused: reuse each h read for 3 FMAs) ----
    {
        float2 av[8], aq[8], ak[8];
#pragma unroll
        for (int p = 0; p < 8; ++p) {
            av[p] = make_float2(0.f, 0.f);
            aq[p] = make_float2(0.f, 0.f);
            ak[p] = make_float2(0.f, 0.f);
        }
#pragma unroll 2
        for (int k = 0; k < HID; ++k) {
            float wv = vw[k * HID + t];
            float wq = qw[k * HID + t];
            float wk = kw[k * HID + t];
            float2 wv2 = make_float2(wv, wv);
            float2 wq2 = make_float2(wq, wq);
            float2 wk2 = make_float2(wk, wk);
            const float2* xr = reinterpret_cast<const float2*>(sHT + k * STR + rbase);
#pragma unroll
            for (int p = 0; p < 8; ++p) {
                float2 h2 = xr[p];
                av[p] = ffma2v(h2, wv2, av[p]);
                aq[p] = ffma2v(h2, wq2, aq[p]);
                ak[p] = ffma2v(h2, wk2, ak[p]);
            }
        }
        float bv = vb[t], bq = qb[t], bk = kb[t];
#pragma unroll
        for (int p = 0; p < 8; ++p) {
            float2 r;
            r.x = fmaxf(av[p].x + bv, 0.f); r.y = fmaxf(av[p].y + bv, 0.f);
            *reinterpret_cast<float2*>(sVT + t * STR + rbase + 2 * p) = r;
            r.x = fmaxf(aq[p].x + bq, 0.f); r.y = fmaxf(aq[p].y + bq, 0.f);
            *reinterpret_cast<float2*>(sQT + t * STR + rbase + 2 * p) = r;
            r.x = fmaxf(ak[p].x + bk, 0.f); r.y = fmaxf(ak[p].y + bk, 0.f);
            *reinterpret_cast<float2*>(sKT + t * STR + rbase + 2 * p) = r;
        }
    }
    __syncthreads();

    // ---- scores + mask: logits[i][j] = q_i . k_j masked; write transposed sPT[j][i] ----
    {
        const int j  = tid & 31;     // lane: key index
        const int ib = tid >> 5;     // warp: base query row
        float sc0 = 0.f, sc1 = 0.f, sc2 = 0.f, sc3 = 0.f;
#pragma unroll 4
        for (int h = 0; h < HID; ++h) {
            float kv = sKT[h * STR + j];
            sc0 = fmaf(sQT[h * STR + ib],      kv, sc0);
            sc1 = fmaf(sQT[h * STR + ib + 8],  kv, sc1);
            sc2 = fmaf(sQT[h * STR + ib + 16], kv, sc2);
            sc3 = fmaf(sQT[h * STR + ib + 24], kv, sc3);
        }
        float sc[4] = {sc0, sc1, sc2, sc3};
#pragma unroll
        for (int r = 0; r < 4; ++r) {
            int i = ib + 8 * r;
            float m = sMK[i * NAG + j];
            sPT[j * STR + i] = sc[r] * m - NEGV * (1.0f - m);
        }
    }
    __syncthreads();

    // ---- softmax over j for each row i (warp 0; lane = row) ----
    if (tid < NAG) {
        const int i = tid;
        float mx = sPT[0 * STR + i];
#pragma unroll
        for (int j = 1; j < NAG; ++j) mx = fmaxf(mx, sPT[j * STR + i]);
        float s = 0.f;
#pragma unroll
        for (int j = 0; j < NAG; ++j) {
            float e = expf(sPT[j * STR + i] - mx);
            sPT[j * STR + i] = e;
            s += e;
        }
        float inv = 1.0f / s;
#pragma unroll
        for (int j = 0; j < NAG; ++j) sPT[j * STR + i] *= inv;
    }
    __syncthreads();

    // ---- out = P @ V  ->  sXT (transposed) ----
    {
        float2 acc[8];
#pragma unroll
        for (int p = 0; p < 8; ++p) acc[p] = make_float2(0.f, 0.f);
#pragma unroll 2
        for (int j = 0; j < NAG; ++j) {
            float v = sVT[t * STR + j];
            float2 v2 = make_float2(v, v);
            const float2* pr = reinterpret_cast<const float2*>(sPT + j * STR + rbase);
#pragma unroll
            for (int p = 0; p < 8; ++p) acc[p] = ffma2v(pr[p], v2, acc[p]);
        }
#pragma unroll
        for (int p = 0; p < 8; ++p)
            *reinterpret_cast<float2*>(sXT + t * STR + rbase + 2 * p) = acc[p];
    }
    __syncthreads();

    // ---- h' = relu(out @ ow + ob) -> sHT ----
    proj_f32x2<true>(sXT, HID, ow, ob, sHT, t, rbase);
    __syncthreads();
}

__global__ void __launch_bounds__(256, 2)
dgn_kernel(const float* __restrict__ x, const float* __restrict__ mask,
           const float* __restrict__ enc_w, const float* __restrict__ enc_b,
           const float* __restrict__ a1_vw, const float* __restrict__ a1_vb,
           const float* __restrict__ a1_kw, const float* __restrict__ a1_kb,
           const float* __restrict__ a1_qw, const float* __restrict__ a1_qb,
           const float* __restrict__ a1_ow, const float* __restrict__ a1_ob,
           const float* __restrict__ a2_vw, const float* __restrict__ a2_vb,
           const float* __restrict__ a2_kw, const float* __restrict__ a2_kb,
           const float* __restrict__ a2_qw, const float* __restrict__ a2_qb,
           const float* __restrict__ a2_ow, const float* __restrict__ a2_ob,
           const float* __restrict__ qhw, const float* __restrict__ qhb,
           float* __restrict__ out)
{
    extern __shared__ float sm[];
    float* sXT = sm + OFF_XT;
    float* sHT = sm + OFF_HT;
    float* sMK = sm + OFF_MK;

    const int b   = blockIdx.x;
    const int tid = threadIdx.x;
    const int t     = tid & 127;
    const int rbase = (tid >> 7) << 4;

    // ---- load x (transposed into smem) and mask ----
    {
        const float4* xg = reinterpret_cast<const float4*>(x + (size_t)b * NAG * DIN);
#pragma unroll 2
        for (int idx = tid; idx < NAG * DIN / 4; idx += 256) {
            float4 v = xg[idx];
            int lin = idx * 4;
            int i = lin >> 8;       // / DIN
            int d = lin & 255;      // % DIN
            sXT[(d + 0) * STR + i] = v.x;
            sXT[(d + 1) * STR + i] = v.y;
            sXT[(d + 2) * STR + i] = v.z;
            sXT[(d + 3) * STR + i] = v.w;
        }
        const float4* mg = reinterpret_cast<const float4*>(mask + (size_t)b * NAG * NAG);
        reinterpret_cast<float4*>(sMK)[tid] = mg[tid];  // 1024 floats == 256 float4
    }
    __syncthreads();

    // ---- encoder: h1 = relu(x @ enc_w + enc_b) ----
    proj_f32x2<true>(sXT, DIN, enc_w, enc_b, sHT, t, rbase);
    __syncthreads();

    // ---- two attention blocks ----
    att_block(sm, a1_vw, a1_vb, a1_kw, a1_kb, a1_qw, a1_qb, a1_ow, a1_ob, tid);
    att_block(sm, a2_vw, a2_vb, a2_kw, a2_kb, a2_qw, a2_qb, a2_ow, a2_ob, tid);

    // ---- head: q = h3 @ q_w + q_b  [32,32] ----
    {
        const int a  = tid & 31;
        const int ig = tid >> 5;
        float acc[4] = {0.f, 0.f, 0.f, 0.f};
#pragma unroll 4
        for (int d = 0; d < HID; ++d) {
            float w = qhw[d * NACT + a];
            acc[0] = fmaf(sHT[d * STR + ig],      w, acc[0]);
            acc[1] = fmaf(sHT[d * STR + ig + 8],  w, acc[1]);
            acc[2] = fmaf(sHT[d * STR + ig + 16], w, acc[2]);
            acc[3] = fmaf(sHT[d * STR + ig + 24], w, acc[3]);
        }
        float bb = qhb[a];
        float* og = out + (size_t)b * NAG * NACT;
#pragma unroll
        for (int r = 0; r < 4; ++r)
            og[(ig + 8 * r) * NACT + a] = acc[r] + bb;
    }
}

extern "C" void kernel_launch(void* const* d_in, const int* in_sizes, int n_in,
                              void* d_out, int out_size)
{
    const float* x     = (const float*)d_in[0];
    const float* mask  = (const float*)d_in[1];
    const float* enc_w = (const float*)d_in[2];
    const float* enc_b = (const float*)d_in[3];
    const float* a1_vw = (const float*)d_in[4];
    const float* a1_vb = (const float*)d_in[5];
    const float* a1_kw = (const float*)d_in[6];
    const float* a1_kb = (const float*)d_in[7];
    const float* a1_qw = (const float*)d_in[8];
    const float* a1_qb = (const float*)d_in[9];
    const float* a1_ow = (const float*)d_in[10];
    const float* a1_ob = (const float*)d_in[11];
    const float* a2_vw = (const float*)d_in[12];
    const float* a2_vb = (const float*)d_in[13];
    const float* a2_kw = (const float*)d_in[14];
    const float* a2_kb = (const float*)d_in[15];
    const float* a2_qw = (const float*)d_in[16];
    const float* a2_qb = (const float*)d_in[17];
    const float* a2_ow = (const float*)d_in[18];
    const float* a2_ob = (const float*)d_in[19];
    const float* q_w   = (const float*)d_in[20];
    const float* q_b   = (const float*)d_in[21];

    cudaFuncSetAttribute(dgn_kernel, cudaFuncAttributeMaxDynamicSharedMemorySize, SMEM_BYTES);

    dgn_kernel<<<4096, 256, SMEM_BYTES>>>(
        x, mask, enc_w, enc_b,
        a1_vw, a1_vb, a1_kw, a1_kb, a1_qw, a1_qb, a1_ow, a1_ob,
        a2_vw, a2_vb, a2_kw, a2_kb, a2_qw, a2_qb, a2_ow, a2_ob,
        q_w, q_b, (float*)d_out);
}